// round 1
// baseline (speedup 1.0000x reference)
#include <cuda_runtime.h>

#define DD 128
#define NMAX 100000
#define EMAX 640000

// ---------------- scratch (static device globals; no runtime allocation) ----
__device__ __align__(16) float g_h1[NMAX * DD];
__device__ __align__(16) float g_conv[NMAX * DD];
__device__ __align__(16) float g_agg[NMAX * DD];
__device__ float g_sdeg[NMAX];
__device__ float g_rdeg[NMAX];
__device__ __align__(16) float g_gvec[DD];
__device__ float g_an[DD];

// ---------------- zero scratch ---------------------------------------------
__global__ void zero_kernel(int n)
{
    int stride = gridDim.x * blockDim.x;
    int i = blockIdx.x * blockDim.x + threadIdx.x;
    float4 z = make_float4(0.f, 0.f, 0.f, 0.f);
    int total4 = n * (DD / 4);
    float4* agg4 = reinterpret_cast<float4*>(g_agg);
    for (int t = i; t < total4; t += stride) agg4[t] = z;
    for (int t = i; t < n; t += stride) { g_sdeg[t] = 0.f; g_rdeg[t] = 0.f; }
    if (i < DD) g_an[i] = 0.f;
}

// ---------------- degree counts --------------------------------------------
__global__ void deg_kernel(const int* __restrict__ snd, const int* __restrict__ rcv, int e)
{
    int stride = gridDim.x * blockDim.x;
    for (int t = blockIdx.x * blockDim.x + threadIdx.x; t < e; t += stride) {
        atomicAdd(&g_sdeg[snd[t]], 1.f);
        atomicAdd(&g_rdeg[rcv[t]], 1.f);
    }
}

// ---------------- gvec = globals @ W3 + b3 ---------------------------------
__global__ void gvec_kernel(const float* __restrict__ gl,
                            const float* __restrict__ W3,
                            const float* __restrict__ b3)
{
    __shared__ float sg[DD];
    int j = threadIdx.x;
    sg[j] = gl[j];
    __syncthreads();
    float s = b3[j];
#pragma unroll 8
    for (int k = 0; k < DD; ++k) s = fmaf(sg[k], W3[k * DD + j], s);
    g_gvec[j] = s;
}

// ---------------- fused dual GEMM: h1 = A@W1+b1 ; conv = (A@W2+b2)*rs -------
// Block tile: 64 rows x 128 cols, full K=128 resident in smem.
// 128 threads, thread tile 4 rows x 16 cols.
// f32x2 packed FMA: accumulators paired along columns, b-pairs loaded directly
// as u64 from smem (no pack cost); only the broadcast 'a' needs mov.b64 {a,a}.
#define GEMM_SMEM ((64 * 132 + 128 * 128) * 4)

__global__ __launch_bounds__(128, 2) void gemm_kernel(
    const float* __restrict__ nodes,
    const float* __restrict__ W1, const float* __restrict__ b1,
    const float* __restrict__ W2, const float* __restrict__ b2,
    int n)
{
    extern __shared__ float smem[];
    float* As = smem;                 // [64][132] padded
    float* Bs = smem + 64 * 132;      // [128][128]
    const int tid = threadIdx.x;
    const int rg = tid >> 3;          // 0..15 -> rows rg*4..rg*4+3
    const int cg = tid & 7;           // 0..7  -> cols cg*16..cg*16+15
    const int block_row0 = blockIdx.x * 64;
    const int rowbase = block_row0 + rg * 4;
    const int colbase = cg * 16;

    // load A tile (zero-fill OOB rows)
    for (int t = tid; t < 64 * 32; t += 128) {
        int r = t >> 5;
        int c4 = (t & 31) << 2;
        float4 v = make_float4(0.f, 0.f, 0.f, 0.f);
        if (block_row0 + r < n)
            v = *reinterpret_cast<const float4*>(&nodes[(size_t)(block_row0 + r) * DD + c4]);
        *reinterpret_cast<float4*>(&As[r * 132 + c4]) = v;
    }

#pragma unroll
    for (int pass = 0; pass < 2; ++pass) {
        const float* __restrict__ W    = pass ? W2 : W1;
        const float* __restrict__ bias = pass ? b2 : b1;
        __syncthreads();   // prior readers of Bs done / As ready (pass 0)
        for (int t = tid; t < DD * 32; t += 128) {
            *reinterpret_cast<float4*>(&Bs[t << 2]) =
                *reinterpret_cast<const float4*>(&W[t << 2]);
        }
        __syncthreads();

        unsigned long long acc[32];
#pragma unroll
        for (int i = 0; i < 32; ++i) acc[i] = 0ull;

#pragma unroll 8
        for (int k = 0; k < DD; ++k) {
            unsigned long long bb[8];
#pragma unroll
            for (int m = 0; m < 4; ++m) {
                ulonglong2 bv = *reinterpret_cast<const ulonglong2*>(
                    &Bs[k * DD + colbase + m * 4]);
                bb[2 * m]     = bv.x;
                bb[2 * m + 1] = bv.y;
            }
#pragma unroll
            for (int i = 0; i < 4; ++i) {
                float a = As[(rg * 4 + i) * 132 + k];
                unsigned long long aa;
                asm("mov.b64 %0, {%1, %1};" : "=l"(aa) : "f"(a));
#pragma unroll
                for (int j = 0; j < 8; ++j)
                    asm("fma.rn.f32x2 %0, %1, %2, %0;"
                        : "+l"(acc[i * 8 + j]) : "l"(aa), "l"(bb[j]));
            }
        }

        float bloc[16];
#pragma unroll
        for (int c = 0; c < 16; ++c) bloc[c] = bias[colbase + c];
        float* __restrict__ dst = pass ? g_conv : g_h1;
#pragma unroll
        for (int i = 0; i < 4; ++i) {
            int row = rowbase + i;
            if (row < n) {
                float rs = 1.f;
                if (pass) rs = rsqrtf(fmaxf(g_sdeg[row], 1.f));
                float v[16];
#pragma unroll
                for (int j = 0; j < 8; ++j) {
                    float lo, hi;
                    asm("mov.b64 {%0, %1}, %2;" : "=f"(lo), "=f"(hi) : "l"(acc[i * 8 + j]));
                    v[2 * j]     = (lo + bloc[2 * j]) * rs;
                    v[2 * j + 1] = (hi + bloc[2 * j + 1]) * rs;
                }
#pragma unroll
                for (int q = 0; q < 4; ++q)
                    *reinterpret_cast<float4*>(&dst[(size_t)row * DD + colbase + q * 4]) =
                        make_float4(v[q * 4], v[q * 4 + 1], v[q * 4 + 2], v[q * 4 + 3]);
            }
        }
    }
}

// ---------------- edge scatter: agg[r] += conv[s] (vector atomics) ---------
__global__ void scatter_kernel(const int* __restrict__ snd, const int* __restrict__ rcv, int e)
{
    int lane  = threadIdx.x & 31;
    int warp  = (blockIdx.x * blockDim.x + threadIdx.x) >> 5;
    int nwarp = (gridDim.x * blockDim.x) >> 5;
    for (int ed = warp; ed < e; ed += nwarp) {
        int s = __ldg(&snd[ed]);
        int r = __ldg(&rcv[ed]);
        float4 v = *reinterpret_cast<const float4*>(&g_conv[(size_t)s * DD + lane * 4]);
        float* dst = &g_agg[(size_t)r * DD + lane * 4];
        asm volatile("red.global.add.v4.f32 [%0], {%1, %2, %3, %4};"
                     :: "l"(dst), "f"(v.x), "f"(v.y), "f"(v.z), "f"(v.w) : "memory");
    }
}

// ---------------- fusion: h = relu(h1 + agg*rs + gvec) + nodes; an += h ----
__global__ void fuse_kernel(const float* __restrict__ nodes, float* __restrict__ out, int n)
{
    __shared__ float s_an[DD];
    if (threadIdx.x < DD) s_an[threadIdx.x] = 0.f;
    __syncthreads();
    int gt = blockIdx.x * blockDim.x + threadIdx.x;
    int stride = gridDim.x * blockDim.x;     // multiple of 32 -> column invariant
    int c4 = (gt & 31) * 4;
    float4 gv = *reinterpret_cast<const float4*>(&g_gvec[c4]);
    float4 part = make_float4(0.f, 0.f, 0.f, 0.f);
    int total = n * 32;
    for (int t = gt; t < total; t += stride) {
        int node = t >> 5;
        size_t off = (size_t)node * DD + c4;
        float rs = rsqrtf(fmaxf(g_rdeg[node], 1.f));
        float4 h1 = *reinterpret_cast<const float4*>(&g_h1[off]);
        float4 ag = *reinterpret_cast<const float4*>(&g_agg[off]);
        float4 nd = *reinterpret_cast<const float4*>(&nodes[off]);
        float4 h;
        h.x = fmaxf(fmaf(ag.x, rs, h1.x) + gv.x, 0.f) + nd.x;
        h.y = fmaxf(fmaf(ag.y, rs, h1.y) + gv.y, 0.f) + nd.y;
        h.z = fmaxf(fmaf(ag.z, rs, h1.z) + gv.z, 0.f) + nd.z;
        h.w = fmaxf(fmaf(ag.w, rs, h1.w) + gv.w, 0.f) + nd.w;
        *reinterpret_cast<float4*>(&out[off]) = h;
        part.x += h.x; part.y += h.y; part.z += h.z; part.w += h.w;
    }
    atomicAdd(&s_an[c4 + 0], part.x);
    atomicAdd(&s_an[c4 + 1], part.y);
    atomicAdd(&s_an[c4 + 2], part.z);
    atomicAdd(&s_an[c4 + 3], part.w);
    __syncthreads();
    if (threadIdx.x < DD) atomicAdd(&g_an[threadIdx.x], s_an[threadIdx.x]);
}

// ---------------- global update: g_new = gl + relu([an, gl] @ Wg + bg) -----
__global__ void gupdate_kernel(const float* __restrict__ gl,
                               const float* __restrict__ Wg,
                               const float* __restrict__ bg,
                               float* __restrict__ out, int n)
{
    __shared__ float sin_[2 * DD];
    int j = threadIdx.x;
    sin_[j]      = g_an[j];
    sin_[DD + j] = gl[j];
    __syncthreads();
    float s = bg[j];
#pragma unroll 8
    for (int k = 0; k < 2 * DD; ++k) s = fmaf(sin_[k], Wg[k * DD + j], s);
    out[(size_t)n * DD + j] = gl[j] + fmaxf(s, 0.f);
}

// ---------------- launcher --------------------------------------------------
extern "C" void kernel_launch(void* const* d_in, const int* in_sizes, int n_in,
                              void* d_out, int out_size)
{
    const float* nodes    = (const float*)d_in[0];
    const float* globals_ = (const float*)d_in[1];
    const int*   senders  = (const int*)d_in[2];
    const int*   receivers= (const int*)d_in[3];
    const float* W1w = (const float*)d_in[4];
    const float* W1b = (const float*)d_in[5];
    const float* W2w = (const float*)d_in[6];
    const float* W2b = (const float*)d_in[7];
    const float* W3w = (const float*)d_in[8];
    const float* W3b = (const float*)d_in[9];
    const float* Wgw = (const float*)d_in[10];
    const float* Wgb = (const float*)d_in[11];
    float* out = (float*)d_out;
    int n = in_sizes[0] / DD;
    int e = in_sizes[2];

    cudaFuncSetAttribute(gemm_kernel, cudaFuncAttributeMaxDynamicSharedMemorySize, GEMM_SMEM);

    zero_kernel<<<1024, 256>>>(n);
    deg_kernel<<<592, 256>>>(senders, receivers, e);
    gvec_kernel<<<1, DD>>>(globals_, W3w, W3b);
    gemm_kernel<<<(n + 63) / 64, 128, GEMM_SMEM>>>(nodes, W1w, W1b, W2w, W2b, n);
    scatter_kernel<<<1184, 256>>>(senders, receivers, e);
    fuse_kernel<<<1024, 256>>>(nodes, out, n);
    gupdate_kernel<<<1, DD>>>(globals_, Wgw, Wgb, out, n);
}

// round 5
// speedup vs baseline: 2.0016x; 2.0016x over previous
#include <cuda_runtime.h>

#define DD 128
#define NMAX 100000
#define EMAX 640000
#define APITCH 130

// ---------------- scratch (static device globals; no runtime allocation) ----
__device__ __align__(16) float g_h1[NMAX * DD];
__device__ __align__(16) float g_conv[NMAX * DD];
__device__ __align__(16) float g_agg[NMAX * DD];
__device__ float g_sdeg[NMAX];
__device__ float g_rdeg[NMAX];
__device__ __align__(16) float g_gvec[DD];
__device__ float g_an[DD];

// ---------------- zero scratch ---------------------------------------------
__global__ void zero_kernel(int n)
{
    int stride = gridDim.x * blockDim.x;
    int i = blockIdx.x * blockDim.x + threadIdx.x;
    float4 z = make_float4(0.f, 0.f, 0.f, 0.f);
    int total4 = n * (DD / 4);
    float4* agg4 = reinterpret_cast<float4*>(g_agg);
    for (int t = i; t < total4; t += stride) agg4[t] = z;
    for (int t = i; t < n; t += stride) { g_sdeg[t] = 0.f; g_rdeg[t] = 0.f; }
    if (i < DD) g_an[i] = 0.f;
}

// ---------------- degree counts --------------------------------------------
__global__ void deg_kernel(const int* __restrict__ snd, const int* __restrict__ rcv, int e)
{
    int stride = gridDim.x * blockDim.x;
    for (int t = blockIdx.x * blockDim.x + threadIdx.x; t < e; t += stride) {
        atomicAdd(&g_sdeg[snd[t]], 1.f);
        atomicAdd(&g_rdeg[rcv[t]], 1.f);
    }
}

// ---------------- gvec = globals @ W3 + b3 ---------------------------------
__global__ void gvec_kernel(const float* __restrict__ gl,
                            const float* __restrict__ W3,
                            const float* __restrict__ b3)
{
    __shared__ float sg[DD];
    int j = threadIdx.x;
    sg[j] = gl[j];
    __syncthreads();
    float s = b3[j];
#pragma unroll 8
    for (int k = 0; k < DD; ++k) s = fmaf(sg[k], W3[k * DD + j], s);
    g_gvec[j] = s;
}

// ---------------- dual GEMM: h1 = A@W1+b1 ; conv = (A@W2+b2)*rs -------------
// Block: 128 rows x 64 cols (blockIdx.y picks col half), 256 threads.
// A tile [128][130] loaded ONCE (float2 stores: pitch 130*4=520B is 8B-aligned
// only, so ST.64 not ST.128), reused for both W1 and W2 passes.
// Thread tile 4 rows x 8 cols: rows=(tid>>3)*4.., cols=32*m+4*(tid&7), m=0,1.
// Bank-conflict-free:
//   Bs LDS.128: 8 cg addresses per strip = one contiguous 128B span.
//   As LDS.32 : pitch 130 -> 4 rg-groups/warp hit banks {0,8,16,24}, 8-lane bcast.
#define GEMM_SMEM ((DD * APITCH + DD * 64) * 4)

__global__ __launch_bounds__(256, 2) void gemm_kernel(
    const float* __restrict__ nodes,
    const float* __restrict__ W1, const float* __restrict__ b1,
    const float* __restrict__ W2, const float* __restrict__ b2,
    int n)
{
    extern __shared__ float smem[];
    float* As = smem;                    // [128][130]
    float* Bs = smem + DD * APITCH;      // [128][64]
    const int tid = threadIdx.x;
    const int rg = tid >> 3;             // 0..31
    const int cg = tid & 7;              // 0..7
    const int block_row0 = blockIdx.x * 128;
    const int coloff = blockIdx.y * 64;  // 0 or 64
    const int rowb = rg * 4;
    const int colb = cg * 4;

    // load A tile: 128 rows x 128 cols (zero-fill OOB rows).
    // LDG.128 from gmem; two ST.64 into smem (row pitch is only 8B-aligned).
    for (int t = tid; t < 128 * 32; t += 256) {
        int r  = t >> 5;
        int c4 = (t & 31) << 2;
        float4 v = make_float4(0.f, 0.f, 0.f, 0.f);
        if (block_row0 + r < n)
            v = *reinterpret_cast<const float4*>(&nodes[(size_t)(block_row0 + r) * DD + c4]);
        float* p = &As[r * APITCH + c4];
        *reinterpret_cast<float2*>(p)     = make_float2(v.x, v.y);
        *reinterpret_cast<float2*>(p + 2) = make_float2(v.z, v.w);
    }

#pragma unroll
    for (int pass = 0; pass < 2; ++pass) {
        const float* __restrict__ W    = pass ? W2 : W1;
        const float* __restrict__ bias = pass ? b2 : b1;
        float* __restrict__ dst        = pass ? g_conv : g_h1;

        __syncthreads();   // pass 0: A ready; pass 1: previous Bs readers done
        // load B tile: 128 k x 64 cols from W[:, coloff:coloff+64]
        for (int t = tid; t < 128 * 16; t += 256) {
            int k  = t >> 4;
            int c4 = (t & 15) << 2;
            *reinterpret_cast<float4*>(&Bs[k * 64 + c4]) =
                *reinterpret_cast<const float4*>(&W[k * DD + coloff + c4]);
        }
        __syncthreads();

        unsigned long long acc[16];    // 4 rows x 2 strips x 2 pairs
#pragma unroll
        for (int i = 0; i < 16; ++i) acc[i] = 0ull;

#pragma unroll 8
        for (int k = 0; k < DD; ++k) {
            unsigned long long bb[4];
#pragma unroll
            for (int m = 0; m < 2; ++m) {
                ulonglong2 bv = *reinterpret_cast<const ulonglong2*>(
                    &Bs[k * 64 + colb + 32 * m]);
                bb[2 * m]     = bv.x;
                bb[2 * m + 1] = bv.y;
            }
#pragma unroll
            for (int i = 0; i < 4; ++i) {
                float a = As[(rowb + i) * APITCH + k];
                unsigned long long aa;
                asm("mov.b64 %0, {%1, %1};" : "=l"(aa) : "f"(a));
#pragma unroll
                for (int j = 0; j < 4; ++j)
                    asm("fma.rn.f32x2 %0, %1, %2, %0;"
                        : "+l"(acc[i * 4 + j]) : "l"(aa), "l"(bb[j]));
            }
        }

        // epilogue: thread cols = coloff + 32*m + colb + {0..3}, m in {0,1}
        float bl[8];
#pragma unroll
        for (int m = 0; m < 2; ++m)
#pragma unroll
            for (int c = 0; c < 4; ++c)
                bl[4 * m + c] = __ldg(&bias[coloff + 32 * m + colb + c]);

#pragma unroll
        for (int i = 0; i < 4; ++i) {
            int row = block_row0 + rowb + i;
            if (row < n) {
                float rs = 1.f;
                if (pass) rs = rsqrtf(fmaxf(g_sdeg[row], 1.f));
#pragma unroll
                for (int m = 0; m < 2; ++m) {
                    float lo0, hi0, lo1, hi1;
                    asm("mov.b64 {%0, %1}, %2;" : "=f"(lo0), "=f"(hi0)
                        : "l"(acc[i * 4 + 2 * m]));
                    asm("mov.b64 {%0, %1}, %2;" : "=f"(lo1), "=f"(hi1)
                        : "l"(acc[i * 4 + 2 * m + 1]));
                    float4 v;
                    v.x = (lo0 + bl[4 * m + 0]) * rs;
                    v.y = (hi0 + bl[4 * m + 1]) * rs;
                    v.z = (lo1 + bl[4 * m + 2]) * rs;
                    v.w = (hi1 + bl[4 * m + 3]) * rs;
                    *reinterpret_cast<float4*>(
                        &dst[(size_t)row * DD + coloff + 32 * m + colb]) = v;
                }
            }
        }
    }
}

// ---------------- edge scatter: agg[r] += conv[s] (vector atomics) ---------
__global__ void scatter_kernel(const int* __restrict__ snd, const int* __restrict__ rcv, int e)
{
    int lane  = threadIdx.x & 31;
    int warp  = (blockIdx.x * blockDim.x + threadIdx.x) >> 5;
    int nwarp = (gridDim.x * blockDim.x) >> 5;
    for (int ed = warp; ed < e; ed += nwarp) {
        int s = __ldg(&snd[ed]);
        int r = __ldg(&rcv[ed]);
        float4 v = *reinterpret_cast<const float4*>(&g_conv[(size_t)s * DD + lane * 4]);
        float* dstp = &g_agg[(size_t)r * DD + lane * 4];
        asm volatile("red.global.add.v4.f32 [%0], {%1, %2, %3, %4};"
                     :: "l"(dstp), "f"(v.x), "f"(v.y), "f"(v.z), "f"(v.w) : "memory");
    }
}

// ---------------- fusion: h = relu(h1 + agg*rs + gvec) + nodes; an += h ----
__global__ void fuse_kernel(const float* __restrict__ nodes, float* __restrict__ out, int n)
{
    __shared__ float s_an[DD];
    if (threadIdx.x < DD) s_an[threadIdx.x] = 0.f;
    __syncthreads();
    int gt = blockIdx.x * blockDim.x + threadIdx.x;
    int stride = gridDim.x * blockDim.x;
    int c4 = (gt & 31) * 4;
    float4 gv = *reinterpret_cast<const float4*>(&g_gvec[c4]);
    float4 part = make_float4(0.f, 0.f, 0.f, 0.f);
    int total = n * 32;
    for (int t = gt; t < total; t += stride) {
        int node = t >> 5;
        size_t off = (size_t)node * DD + c4;
        float rs = rsqrtf(fmaxf(g_rdeg[node], 1.f));
        float4 h1 = *reinterpret_cast<const float4*>(&g_h1[off]);
        float4 ag = *reinterpret_cast<const float4*>(&g_agg[off]);
        float4 nd = *reinterpret_cast<const float4*>(&nodes[off]);
        float4 h;
        h.x = fmaxf(fmaf(ag.x, rs, h1.x) + gv.x, 0.f) + nd.x;
        h.y = fmaxf(fmaf(ag.y, rs, h1.y) + gv.y, 0.f) + nd.y;
        h.z = fmaxf(fmaf(ag.z, rs, h1.z) + gv.z, 0.f) + nd.z;
        h.w = fmaxf(fmaf(ag.w, rs, h1.w) + gv.w, 0.f) + nd.w;
        *reinterpret_cast<float4*>(&out[off]) = h;
        part.x += h.x; part.y += h.y; part.z += h.z; part.w += h.w;
    }
    atomicAdd(&s_an[c4 + 0], part.x);
    atomicAdd(&s_an[c4 + 1], part.y);
    atomicAdd(&s_an[c4 + 2], part.z);
    atomicAdd(&s_an[c4 + 3], part.w);
    __syncthreads();
    if (threadIdx.x < DD) atomicAdd(&g_an[threadIdx.x], s_an[threadIdx.x]);
}

// ---------------- global update: g_new = gl + relu([an, gl] @ Wg + bg) -----
__global__ void gupdate_kernel(const float* __restrict__ gl,
                               const float* __restrict__ Wg,
                               const float* __restrict__ bg,
                               float* __restrict__ out, int n)
{
    __shared__ float sin_[2 * DD];
    int j = threadIdx.x;
    sin_[j]      = g_an[j];
    sin_[DD + j] = gl[j];
    __syncthreads();
    float s = bg[j];
#pragma unroll 8
    for (int k = 0; k < 2 * DD; ++k) s = fmaf(sin_[k], Wg[k * DD + j], s);
    out[(size_t)n * DD + j] = gl[j] + fmaxf(s, 0.f);
}

// ---------------- launcher --------------------------------------------------
extern "C" void kernel_launch(void* const* d_in, const int* in_sizes, int n_in,
                              void* d_out, int out_size)
{
    const float* nodes    = (const float*)d_in[0];
    const float* globals_ = (const float*)d_in[1];
    const int*   senders  = (const int*)d_in[2];
    const int*   receivers= (const int*)d_in[3];
    const float* W1w = (const float*)d_in[4];
    const float* W1b = (const float*)d_in[5];
    const float* W2w = (const float*)d_in[6];
    const float* W2b = (const float*)d_in[7];
    const float* W3w = (const float*)d_in[8];
    const float* W3b = (const float*)d_in[9];
    const float* Wgw = (const float*)d_in[10];
    const float* Wgb = (const float*)d_in[11];
    float* out = (float*)d_out;
    int n = in_sizes[0] / DD;
    int e = in_sizes[2];

    cudaFuncSetAttribute(gemm_kernel, cudaFuncAttributeMaxDynamicSharedMemorySize, GEMM_SMEM);

    zero_kernel<<<1024, 256>>>(n);
    deg_kernel<<<592, 256>>>(senders, receivers, e);
    gvec_kernel<<<1, DD>>>(globals_, W3w, W3b);
    dim3 grid((n + 127) / 128, 2);
    gemm_kernel<<<grid, 256, GEMM_SMEM>>>(nodes, W1w, W1b, W2w, W2b, n);
    scatter_kernel<<<1184, 256>>>(senders, receivers, e);
    fuse_kernel<<<1024, 256>>>(nodes, out, n);
    gupdate_kernel<<<1, DD>>>(globals_, Wgw, Wgb, out, n);
}